// round 13
// baseline (speedup 1.0000x reference)
#include <cuda_runtime.h>
#include <cuda_bf16.h>
#include <cstdint>
#include <cstddef>

#define B_ 4
#define L_ 1024
#define D_ 1024
#define H_ 16
#define F_ 4096
#define S_ 4
#define LP_ (L_ + 4)

// ---------------- scratch (device globals; no allocation allowed) -------------
__device__ float g_xpad[B_ * LP_ * D_];
__device__ float g_xc[B_ * L_ * D_];
__device__ float g_sc1[B_ * 512 * D_];
__device__ float g_sc2[B_ * 256 * D_];
__device__ float g_sc3[B_ * 128 * D_];
__device__ float g_qkv[(size_t)B_ * L_ * 6 * D_];       // [row][ Q(4*1024) | K0 | V0 ]
__device__ float g_kvb[(size_t)B_ * 512 * 2 * D_];      // K|V for s>=1 (max M=2048)
__device__ float g_ob[B_ * L_ * D_];
__device__ float g_maha[B_ * L_ * D_];
__device__ float g_x1[B_ * L_ * D_];
__device__ float g_ffn[(size_t)B_ * L_ * F_];
__device__ float g_w[S_];
// transposed weights ([N][K] row-major), pre-rounded to tf32
__device__ float g_wdcT[3 * D_ * D_];                   // [o][tap][i]
__device__ float g_wdecT[6 * D_ * D_];                  // [s][o][tap][i]
__device__ float g_wbig[(size_t)6 * D_ * D_];           // [WqT(4 scales) ; Wk0T ; WvT]
__device__ float g_wkvT[(size_t)3 * 2 * D_ * D_];       // s=1..3: [WkT ; WvT]
__device__ float g_woT[D_ * D_];
__device__ float g_w1T[(size_t)D_ * F_];                // [F][D]
__device__ float g_w2T[(size_t)D_ * F_];                // [D][F]

// ---------------- helpers ----------------
__device__ __forceinline__ float tf32r(float x) {
    float r;
    asm("cvt.rna.tf32.f32 %0, %1;" : "=f"(r) : "f"(x));
    return r;
}
__device__ __forceinline__ void mma_tf32(float (&d)[4], const uint32_t (&a)[4],
                                         const uint32_t (&b)[2]) {
    asm volatile(
        "mma.sync.aligned.m16n8k8.row.col.f32.tf32.tf32.f32 "
        "{%0,%1,%2,%3}, {%4,%5,%6,%7}, {%8,%9}, {%0,%1,%2,%3};"
        : "+f"(d[0]), "+f"(d[1]), "+f"(d[2]), "+f"(d[3])
        : "r"(a[0]), "r"(a[1]), "r"(a[2]), "r"(a[3]), "r"(b[0]), "r"(b[1]));
}
__device__ __forceinline__ void cp16(float* smem, const float* g) {
    uint32_t s = (uint32_t)__cvta_generic_to_shared(smem);
    asm volatile("cp.async.cg.shared.global [%0], [%1], 16;" :: "r"(s), "l"(g));
}
#define CP_COMMIT() asm volatile("cp.async.commit_group;" ::: "memory")
#define CP_WAIT1()  asm volatile("cp.async.wait_group 1;" ::: "memory")
#define CP_WAIT0()  asm volatile("cp.async.wait_group 0;" ::: "memory")

#define SSTR 36               // R7-proven layout: 16B stores conflict-free
#define STAGE_FLOATS (2 * 128 * SSTR)          // 9216 floats = 36864 B
#define GEMM_SMEM_BYTES (3 * STAGE_FLOATS * 4) // 110592 (3-stage ring)

// ---------------- tf32 mma.sync GEMM: 4 warps x (64x64) warp tiles ------------
// C[M,N] = act(alpha * A' @ BT^T [+bias] [+C]) ; row remap for conv-as-GEMM.
__global__ __launch_bounds__(128, 2) void mh_gemm_mma(
    const float* __restrict__ A, const float* __restrict__ BT, float* __restrict__ C,
    int M, int N, int Ktot, int lda, int KperTap, int tapOffRow,
    int Lout, int Lin, int strideL, int offRow,
    const float* __restrict__ bias, const float* __restrict__ alphaPtr,
    int accumulate, int act, int roundOut)
{
    extern __shared__ __align__(16) float dsm[];
    const int tid = threadIdx.x;
    const int lane = tid & 31;
    const int wid = tid >> 5;
    const int wr = wid >> 1;   // warp row 0..1 (64 rows each)
    const int wc = wid & 1;    // warp col 0..1 (64 cols each)
    const int rowBase = blockIdx.y * 128;
    const int colBase = blockIdx.x * 128;

    // loader: 2048 float4 slots (A 1024 + B 1024), 16 per thread
    const float* aBase[8];
    const float* bBase[8];
    int sOff[8];
#pragma unroll
    for (int i = 0; i < 8; i++) {
        int idx = tid + i * 128;
        int row = idx >> 3, c4 = idx & 7;
        sOff[i] = row * SSTR + c4 * 4;
        int gr = rowBase + row;
        int ar = (gr / Lout) * Lin + (gr % Lout) * strideL + offRow;
        aBase[i] = A + (size_t)ar * lda + c4 * 4;
        bBase[i] = BT + (size_t)(colBase + row) * Ktot + c4 * 4;
    }

    float acc[4][8][4];
#pragma unroll
    for (int mt = 0; mt < 4; mt++)
#pragma unroll
        for (int nt = 0; nt < 8; nt++)
#pragma unroll
            for (int j = 0; j < 4; j++) acc[mt][nt][j] = 0.0f;

    const int T = Ktot / 32;

    auto load_stage = [&](int st, int k0) {
        int tap = k0 / KperTap;
        size_t aAdd = (size_t)tap * tapOffRow * lda + (k0 - tap * KperTap);
        float* As = dsm + st * STAGE_FLOATS;
        float* Bs = As + 128 * SSTR;
#pragma unroll
        for (int i = 0; i < 8; i++) {
            cp16(As + sOff[i], aBase[i] + aAdd);
            cp16(Bs + sOff[i], bBase[i] + k0);
        }
    };

    load_stage(0, 0); CP_COMMIT();
    if (T > 1) { load_stage(1, 32); CP_COMMIT(); }

    const int quad = lane >> 2;
    const int tq = lane & 3;

    for (int t = 0; t < T; t++) {
        if (t + 1 < T) CP_WAIT1(); else CP_WAIT0();
        __syncthreads();

        const int st = t % 3;
        const float* As = dsm + st * STAGE_FLOATS;
        const float* Bs = As + 128 * SSTR;
#pragma unroll
        for (int ks = 0; ks < 4; ks++) {
            uint32_t af[4][4], bf[8][2];
#pragma unroll
            for (int mt = 0; mt < 4; mt++) {
                int r = wr * 64 + mt * 16 + quad;
                const float* p = As + r * SSTR + ks * 8 + tq;
                af[mt][0] = __float_as_uint(p[0]);
                af[mt][1] = __float_as_uint(p[8 * SSTR]);
                af[mt][2] = __float_as_uint(p[4]);
                af[mt][3] = __float_as_uint(p[8 * SSTR + 4]);
            }
#pragma unroll
            for (int nt = 0; nt < 8; nt++) {
                int n = wc * 64 + nt * 8 + quad;
                const float* p = Bs + n * SSTR + ks * 8 + tq;
                bf[nt][0] = __float_as_uint(p[0]);
                bf[nt][1] = __float_as_uint(p[4]);
            }
#pragma unroll
            for (int mt = 0; mt < 4; mt++)
#pragma unroll
                for (int nt = 0; nt < 8; nt++)
                    mma_tf32(acc[mt][nt], af[mt], bf[nt]);
        }

        if (t + 2 < T) { load_stage((t + 2) % 3, (t + 2) * 32); CP_COMMIT(); }
    }

    const float alpha = alphaPtr ? __ldg(alphaPtr) : 1.0f;
#pragma unroll
    for (int mt = 0; mt < 4; mt++) {
#pragma unroll
        for (int nt = 0; nt < 8; nt++) {
            int row = rowBase + wr * 64 + mt * 16 + quad;
            int col = colBase + wc * 64 + nt * 8 + tq * 2;
#pragma unroll
            for (int h = 0; h < 2; h++) {
                int r = row + h * 8;
                float v0 = alpha * acc[mt][nt][h * 2 + 0];
                float v1 = alpha * acc[mt][nt][h * 2 + 1];
                if (bias) { v0 += bias[col]; v1 += bias[col + 1]; }
                float* cp = C + (size_t)r * N + col;
                if (accumulate) { v0 += cp[0]; v1 += cp[1]; }
                if (act == 1) { v0 = fmaxf(v0, 0.0f); v1 = fmaxf(v1, 0.0f); }
                else if (act == 2) {
                    v0 = 0.5f * v0 * (1.0f + erff(v0 * 0.70710678118654752440f));
                    v1 = 0.5f * v1 * (1.0f + erff(v1 * 0.70710678118654752440f));
                }
                if (roundOut) { v0 = tf32r(v0); v1 = tf32r(v1); }
                *(float2*)cp = make_float2(v0, v1);
            }
        }
    }
}

// ---------------- tensor-core flash attention (64q x 64k tiles) ---------------
// Inputs q/kv are pre-rounded to tf32. Output (+)= alpha*softmax(QK^T/8)@V,
// rounded to tf32 (feeds only the Wo GEMM).
#define ASTR 72
#define ATT_SMEM ((4 * 64 * ASTR + 192) * 4)
__global__ __launch_bounds__(128) void mh_attn_mma(
    const float* __restrict__ q, int qld, int qoff,
    const float* __restrict__ kv, int kvld,
    float* __restrict__ o, int Ls,
    const float* __restrict__ alphaPtr, int accumulate)
{
    extern __shared__ __align__(16) float sm[];
    float* qs = sm;
    float* ks = qs + 64 * ASTR;
    float* vs = ks + 64 * ASTR;
    float* ps = vs + 64 * ASTR;
    float* s_max = ps + 64 * ASTR;
    float* s_lsum = s_max + 64;
    float* s_corr = s_lsum + 64;

    const int tid = threadIdx.x;
    const int lane = tid & 31;
    const int w = tid >> 5;
    const int quad = lane >> 2, tq = lane & 3;
    const int b = blockIdx.z, h = blockIdx.y;
    const int q0 = blockIdx.x * 64;
    const int rbase = w * 16;

#pragma unroll
    for (int it = 0; it < 8; it++) {
        int i = tid + it * 128;
        int r = i >> 4, dg = (i & 15) * 4;
        float4 t4 = *(const float4*)(q + (size_t)(b * L_ + q0 + r) * qld + qoff + h * 64 + dg);
        *(float4*)(qs + r * ASTR + dg) = t4;
    }
    if (tid < 64) { s_max[tid] = -1e30f; s_lsum[tid] = 0.0f; }

    float oacc[8][4];
#pragma unroll
    for (int nt = 0; nt < 8; nt++)
#pragma unroll
        for (int j = 0; j < 4; j++) oacc[nt][j] = 0.0f;

    for (int kt = 0; kt < Ls; kt += 64) {
        __syncthreads();
#pragma unroll
        for (int it = 0; it < 8; it++) {
            int i = tid + it * 128;
            int key = i >> 4, dg = (i & 15) * 4;
            const float* rowp = kv + (size_t)(b * Ls + kt + key) * kvld;
            *(float4*)(ks + key * ASTR + dg) = *(const float4*)(rowp + h * 64 + dg);
            *(float4*)(vs + key * ASTR + dg) = *(const float4*)(rowp + D_ + h * 64 + dg);
        }
        __syncthreads();

        float sacc[8][4];
#pragma unroll
        for (int nt = 0; nt < 8; nt++)
#pragma unroll
            for (int j = 0; j < 4; j++) sacc[nt][j] = 0.0f;
#pragma unroll
        for (int k8 = 0; k8 < 8; k8++) {
            uint32_t af[4];
            const float* qp = qs + (rbase + quad) * ASTR + k8 * 8 + tq;
            af[0] = __float_as_uint(qp[0]);
            af[1] = __float_as_uint(qp[8 * ASTR]);
            af[2] = __float_as_uint(qp[4]);
            af[3] = __float_as_uint(qp[8 * ASTR + 4]);
#pragma unroll
            for (int nt = 0; nt < 8; nt++) {
                uint32_t bf[2];
                const float* kp = ks + (nt * 8 + quad) * ASTR + k8 * 8 + tq;
                bf[0] = __float_as_uint(kp[0]);
                bf[1] = __float_as_uint(kp[4]);
                mma_tf32(sacc[nt], af, bf);
            }
        }
#pragma unroll
        for (int nt = 0; nt < 8; nt++) {
            float* p0 = ps + (rbase + quad) * ASTR + nt * 8 + 2 * tq;
            float* p1 = ps + (rbase + quad + 8) * ASTR + nt * 8 + 2 * tq;
            *(float2*)p0 = make_float2(sacc[nt][0] * 0.125f, sacc[nt][1] * 0.125f);
            *(float2*)p1 = make_float2(sacc[nt][2] * 0.125f, sacc[nt][3] * 0.125f);
        }
        __syncwarp();

        {
            int r = rbase + (lane & 15);
            int half = lane >> 4;
            float* pr = ps + r * ASTR + half * 32;
            float mx = -1e30f;
#pragma unroll
            for (int j = 0; j < 32; j++) mx = fmaxf(mx, pr[j]);
            mx = fmaxf(mx, __shfl_xor_sync(0xFFFFFFFFu, mx, 16));
            float oldm = s_max[r];
            float newm = fmaxf(oldm, mx);
            float sum = 0.0f;
#pragma unroll
            for (int j = 0; j < 32; j++) {
                float p = __expf(pr[j] - newm);
                pr[j] = tf32r(p);
                sum += p;
            }
            sum += __shfl_xor_sync(0xFFFFFFFFu, sum, 16);
            if (half == 0) {
                float corr = __expf(oldm - newm);
                s_corr[r] = corr;
                s_lsum[r] = s_lsum[r] * corr + sum;
                s_max[r] = newm;
            }
        }
        __syncwarp();

        {
            float c0 = s_corr[rbase + quad];
            float c1 = s_corr[rbase + quad + 8];
#pragma unroll
            for (int nt = 0; nt < 8; nt++) {
                oacc[nt][0] *= c0; oacc[nt][1] *= c0;
                oacc[nt][2] *= c1; oacc[nt][3] *= c1;
            }
        }
#pragma unroll
        for (int k8 = 0; k8 < 8; k8++) {
            uint32_t af[4];
            const float* pp = ps + (rbase + quad) * ASTR + k8 * 8 + tq;
            af[0] = __float_as_uint(pp[0]);
            af[1] = __float_as_uint(pp[8 * ASTR]);
            af[2] = __float_as_uint(pp[4]);
            af[3] = __float_as_uint(pp[8 * ASTR + 4]);
#pragma unroll
            for (int nt = 0; nt < 8; nt++) {
                uint32_t bf[2];
                const float* vp = vs + (k8 * 8 + tq) * ASTR + nt * 8 + quad;
                bf[0] = __float_as_uint(vp[0]);
                bf[1] = __float_as_uint(vp[4 * ASTR]);
                mma_tf32(oacc[nt], af, bf);
            }
        }
    }

    const float alpha = alphaPtr ? __ldg(alphaPtr) : 1.0f;
    const float l0 = alpha / s_lsum[rbase + quad];
    const float l1 = alpha / s_lsum[rbase + quad + 8];
    const int row0 = b * L_ + q0 + rbase + quad;
#pragma unroll
    for (int nt = 0; nt < 8; nt++) {
        int col = h * 64 + nt * 8 + 2 * tq;
        float* p0 = o + (size_t)row0 * D_ + col;
        float* p1 = o + (size_t)(row0 + 8) * D_ + col;
        float2 v0 = make_float2(oacc[nt][0] * l0, oacc[nt][1] * l0);
        float2 v1 = make_float2(oacc[nt][2] * l1, oacc[nt][3] * l1);
        if (accumulate) {
            v0.x += p0[0]; v0.y += p0[1];
            v1.x += p1[0]; v1.y += p1[1];
        }
        v0.x = tf32r(v0.x); v0.y = tf32r(v0.y);
        v1.x = tf32r(v1.x); v1.y = tf32r(v1.y);
        *(float2*)p0 = v0;
        *(float2*)p1 = v1;
    }
}

// ---------------- LayerNorm(a + b) ----------------
__global__ __launch_bounds__(256) void mh_ln(
    const float* __restrict__ a, const float* __restrict__ bsrc,
    const float* __restrict__ g, const float* __restrict__ be,
    float* __restrict__ out)
{
    __shared__ float r1[256], r2[256];
    int row = blockIdx.x;
    const float* ap = a + (size_t)row * D_;
    const float* bp = bsrc + (size_t)row * D_;
    float x[4];
    float s = 0.f, ss = 0.f;
#pragma unroll
    for (int i = 0; i < 4; i++) {
        int idx = threadIdx.x + i * 256;
        x[i] = ap[idx] + bp[idx];
        s += x[i];
        ss += x[i] * x[i];
    }
    int tid = threadIdx.x;
    r1[tid] = s;
    r2[tid] = ss;
    __syncthreads();
    for (int off = 128; off; off >>= 1) {
        if (tid < off) { r1[tid] += r1[tid + off]; r2[tid] += r2[tid + off]; }
        __syncthreads();
    }
    float mu = r1[0] * (1.0f / D_);
    float var = r2[0] * (1.0f / D_) - mu * mu;
    float rstd = rsqrtf(var + 1e-5f);
#pragma unroll
    for (int i = 0; i < 4; i++) {
        int idx = threadIdx.x + i * 256;
        out[(size_t)row * D_ + idx] = (x[i] - mu) * rstd * g[idx] + be[idx];
    }
}

// ---------------- misc small kernels ----------------
__global__ void mh_pad(const float* __restrict__ x, float* __restrict__ xpad)
{
    size_t i = (size_t)blockIdx.x * blockDim.x + threadIdx.x;
    if (i >= (size_t)B_ * LP_ * D_) return;
    int d = (int)(i % D_);
    size_t rl = i / D_;
    int l = (int)(rl % LP_);
    int b = (int)(rl / LP_);
    float val = 0.0f;
    if (l >= 2 && l < L_ + 2)
        val = tf32r(x[((size_t)b * L_ + (l - 2)) * D_ + d]);
    xpad[i] = val;
}

__global__ void mh_twdc(const float* __restrict__ W, float* __restrict__ out)
{
    int id = blockIdx.x * 256 + threadIdx.x;
    if (id >= 3 * D_ * D_) return;
    int i = id & (D_ - 1);
    int tmp = id >> 10;
    int t = tmp % 3;
    int o = tmp / 3;
    out[id] = tf32r(W[((size_t)o * D_ + i) * 3 + t]);
}

__global__ void mh_twdec(const float* __restrict__ W, float* __restrict__ out)
{
    int id = blockIdx.x * 256 + threadIdx.x;
    if (id >= 6 * D_ * D_) return;
    int i = id & (D_ - 1);
    int tmp = id >> 10;
    int t = tmp & 1;
    tmp >>= 1;
    int o = tmp & (D_ - 1);
    int s = tmp >> 10;
    out[id] = tf32r(W[(((size_t)s * D_ + o) * D_ + i) * 2 + t]);
}

// batched transpose with independent z-strides: dst[z][c][r] = tf32(src[z][r][c])
__global__ void mh_transpose(const float* __restrict__ src, float* __restrict__ dst,
                             int R, int C, size_t zsrc, size_t zdst)
{
    __shared__ float t[32][33];
    const float* sp = src + (size_t)blockIdx.z * zsrc;
    float* dp = dst + (size_t)blockIdx.z * zdst;
    int x = blockIdx.x * 32 + threadIdx.x;
    int y0 = blockIdx.y * 32 + threadIdx.y;
#pragma unroll
    for (int j = 0; j < 4; j++) {
        int y = y0 + j * 8;
        if (y < R && x < C) t[threadIdx.y + j * 8][threadIdx.x] = sp[(size_t)y * C + x];
    }
    __syncthreads();
    int x2 = blockIdx.y * 32 + threadIdx.x;
    int y2 = blockIdx.x * 32 + threadIdx.y;
#pragma unroll
    for (int j = 0; j < 4; j++) {
        int y = y2 + j * 8;
        if (y < C && x2 < R) dp[(size_t)y * R + x2] = tf32r(t[threadIdx.x][threadIdx.y + j * 8]);
    }
}

__global__ void mh_agg(const float* __restrict__ logits, float* __restrict__ w,
                       float* __restrict__ aux_out, int has_aux)
{
    if (threadIdx.x == 0 && blockIdx.x == 0) {
        float l[S_], m = -1e30f;
        for (int s = 0; s < S_; s++) { l[s] = logits[s]; m = fmaxf(m, l[s]); }
        float sum = 0.f;
        for (int s = 0; s < S_; s++) { l[s] = expf(l[s] - m); sum += l[s]; }
        float aux = 0.f;
        for (int s = 0; s < S_; s++) {
            float ws = l[s] / sum;
            w[s] = ws;
            aux -= ws * logf(ws + 1e-9f);
        }
        if (has_aux) *aux_out = aux;
    }
}

// ---------------- host launch ----------------
static void launch_tc(const float* A, const float* BT, float* C,
                      int M, int N, int Ktot, int lda, int KperTap, int tapOffRow,
                      int Lout, int Lin, int strideL, int offRow,
                      const float* bias, const float* alphaPtr,
                      int accumulate, int act, int roundOut)
{
    dim3 grid(N / 128, M / 128);
    mh_gemm_mma<<<grid, 128, GEMM_SMEM_BYTES>>>(
        A, BT, C, M, N, Ktot, lda, KperTap, tapOffRow,
        Lout, Lin, strideL, offRow, bias, alphaPtr, accumulate, act, roundOut);
}

extern "C" void kernel_launch(void* const* d_in, const int* in_sizes, int n_in,
                              void* d_out, int out_size)
{
    const float* x      = (const float*)d_in[0];
    const float* W_dc   = (const float*)d_in[1];
    const float* b_dc   = (const float*)d_in[2];
    const float* W_dec  = (const float*)d_in[3];
    const float* Wq     = (const float*)d_in[4];
    const float* Wk     = (const float*)d_in[5];
    const float* Wv     = (const float*)d_in[6];
    const float* Wo     = (const float*)d_in[7];
    const float* agl    = (const float*)d_in[8];
    const float* gamma1 = (const float*)d_in[9];
    const float* beta1  = (const float*)d_in[10];
    const float* gamma2 = (const float*)d_in[11];
    const float* beta2  = (const float*)d_in[12];
    const float* W1     = (const float*)d_in[13];
    const float* b1     = (const float*)d_in[14];
    const float* W2     = (const float*)d_in[15];
    const float* b2     = (const float*)d_in[16];
    float* out = (float*)d_out;

    cudaFuncSetAttribute(mh_gemm_mma, cudaFuncAttributeMaxDynamicSharedMemorySize,
                         GEMM_SMEM_BYTES);
    cudaFuncSetAttribute(mh_attn_mma, cudaFuncAttributeMaxDynamicSharedMemorySize,
                         ATT_SMEM);

    float *xpad, *xc, *sc1, *sc2, *sc3, *qkv, *kvb, *ob, *maha, *x1, *ffn, *wagg;
    float *wdcT, *wdecT, *wbig, *wkvT, *woT, *w1T, *w2T;
    cudaGetSymbolAddress((void**)&xpad, g_xpad);
    cudaGetSymbolAddress((void**)&xc, g_xc);
    cudaGetSymbolAddress((void**)&sc1, g_sc1);
    cudaGetSymbolAddress((void**)&sc2, g_sc2);
    cudaGetSymbolAddress((void**)&sc3, g_sc3);
    cudaGetSymbolAddress((void**)&qkv, g_qkv);
    cudaGetSymbolAddress((void**)&kvb, g_kvb);
    cudaGetSymbolAddress((void**)&ob, g_ob);
    cudaGetSymbolAddress((void**)&maha, g_maha);
    cudaGetSymbolAddress((void**)&x1, g_x1);
    cudaGetSymbolAddress((void**)&ffn, g_ffn);
    cudaGetSymbolAddress((void**)&wagg, g_w);
    cudaGetSymbolAddress((void**)&wdcT, g_wdcT);
    cudaGetSymbolAddress((void**)&wdecT, g_wdecT);
    cudaGetSymbolAddress((void**)&wbig, g_wbig);
    cudaGetSymbolAddress((void**)&wkvT, g_wkvT);
    cudaGetSymbolAddress((void**)&woT, g_woT);
    cudaGetSymbolAddress((void**)&w1T, g_w1T);
    cudaGetSymbolAddress((void**)&w2T, g_w2T);

    const int M = B_ * L_;
    const int has_aux = (out_size > B_ * L_ * D_) ? 1 : 0;
    const size_t DD = (size_t)D_ * D_;

    // prep: weight permutes/transposes (tf32-rounded), agg softmax, padded input
    mh_twdc<<<(3 * D_ * D_ + 255) / 256, 256>>>(W_dc, wdcT);
    mh_twdec<<<(6 * D_ * D_ + 255) / 256, 256>>>(W_dec, wdecT);
    {
        dim3 tb(32, 8);
        // wbig = [WqT for 4 scales ; Wk0T ; WvT]
        mh_transpose<<<dim3(32, 32, 4), tb>>>(Wq, wbig, D_, D_, DD, DD);
        mh_transpose<<<dim3(32, 32, 1), tb>>>(Wk, wbig + 4 * DD, D_, D_, 0, 0);
        mh_transpose<<<dim3(32, 32, 1), tb>>>(Wv, wbig + 5 * DD, D_, D_, 0, 0);
        // wkvT for s=1..3
        mh_transpose<<<dim3(32, 32, 3), tb>>>(Wk + DD, wkvT, D_, D_, DD, 2 * DD);
        mh_transpose<<<dim3(32, 32, 3), tb>>>(Wv, wkvT + DD, D_, D_, 0, 2 * DD);
        mh_transpose<<<dim3(32, 32, 1), tb>>>(Wo, woT, D_, D_, 0, 0);
        mh_transpose<<<dim3(128, 32, 1), tb>>>(W1, w1T, D_, F_, 0, 0);   // -> [F][D]
        mh_transpose<<<dim3(32, 128, 1), tb>>>(W2, w2T, F_, D_, 0, 0);   // -> [D][F]
    }
    mh_agg<<<1, 32>>>(agl, wagg, out + (size_t)B_ * L_ * D_, has_aux);
    mh_pad<<<(B_ * LP_ * D_ + 255) / 256, 256>>>(x, xpad);

    // 1. dilated conv (3 taps folded into K=3072) + bias + ReLU, tf32-rounded out
    launch_tc(xpad, wdcT, xc, M, D_, 3 * D_, D_, D_, 2,
              L_, LP_, 1, 0, b_dc, nullptr, 0, 1, 1);

    // 2. hierarchical decomposition (2 taps folded into K=2048)
    const float* scaleP[S_] = {xc, sc1, sc2, sc3};
    int scaleL[S_] = {L_, L_ / 2, L_ / 4, L_ / 8};
    {
        float* outs[3] = {sc1, sc2, sc3};
        for (int s = 0; s < 3; s++) {
            int Lin = scaleL[s], Lout = scaleL[s + 1];
            launch_tc(scaleP[s], wdecT + (size_t)s * 2 * DD, outs[s],
                      B_ * Lout, D_, 2 * D_, D_, D_, 1,
                      Lout, Lin, 2, 0, nullptr, nullptr, 0, 0, 1);
        }
    }

    // 3a. fused projection: all-scale Q + K0 + V0 in one GEMM -> qkv[M][6144]
    launch_tc(xc, wbig, qkv, M, 6 * D_, D_, D_, D_, 0,
              M, M, 1, 0, nullptr, nullptr, 0, 0, 1);

    // 3b. attention per scale (w_s-weighted, aggregated into ob; Wo applied once)
    for (int s = 0; s < S_; s++) {
        int Ls = scaleL[s];
        const float* kvp;
        int kvld;
        if (s == 0) { kvp = qkv + 4 * D_; kvld = 6 * D_; }
        else {
            int Mk = B_ * Ls;
            launch_tc(scaleP[s], wkvT + (size_t)(s - 1) * 2 * DD, kvb,
                      Mk, 2 * D_, D_, D_, D_, 0,
                      Mk, Mk, 1, 0, nullptr, nullptr, 0, 0, 1);
            kvp = kvb; kvld = 2 * D_;
        }
        dim3 agrid(L_ / 64, H_, B_);
        mh_attn_mma<<<agrid, 128, ATT_SMEM>>>(qkv, 6 * D_, s * D_, kvp, kvld,
                                              ob, Ls, wagg + s, (s > 0) ? 1 : 0);
    }

    // 3c. shared output projection once: maha = ob @ Wo (fp32 out)
    launch_tc(ob, woT, maha, M, D_, D_, D_, D_, 0,
              M, M, 1, 0, nullptr, nullptr, 0, 0, 0);

    // 4. x1 = LN(residual + maha)  (fp32; tf32 truncation happens in-HW at MMA)
    mh_ln<<<M, 256>>>(x, maha, gamma1, beta1, x1);

    // 5. FFN: gelu(x1@W1+b1)@W2+b2, then out = LN(x1 + ffn)
    launch_tc(x1, w1T, ffn, M, F_, D_, D_, D_, 0, M, M, 1, 0, b1, nullptr, 0, 2, 1);
    launch_tc(ffn, w2T, ob, M, D_, F_, F_, F_, 0, M, M, 1, 0, b2, nullptr, 0, 0, 0);
    mh_ln<<<M, 256>>>(x1, ob, gamma2, beta2, out);
}

// round 14
// speedup vs baseline: 1.0057x; 1.0057x over previous
#include <cuda_runtime.h>
#include <cuda_bf16.h>
#include <cstdint>
#include <cstddef>

#define B_ 4
#define L_ 1024
#define D_ 1024
#define H_ 16
#define F_ 4096
#define S_ 4
#define LP_ (L_ + 4)

// ---------------- scratch (device globals; no allocation allowed) -------------
__device__ float g_xpad[B_ * LP_ * D_];
__device__ float g_xc[B_ * L_ * D_];
__device__ float g_sc1[B_ * 512 * D_];
__device__ float g_sc2[B_ * 256 * D_];
__device__ float g_sc3[B_ * 128 * D_];
__device__ float g_qkv[(size_t)B_ * L_ * 6 * D_];       // [row][ Q(4*1024) | K0 | V0 ]
__device__ float g_kvb[(size_t)B_ * 512 * 2 * D_];      // K|V for s>=1 (max M=2048)
__device__ float g_ob[B_ * L_ * D_];
__device__ float g_maha[B_ * L_ * D_];
__device__ float g_x1[B_ * L_ * D_];
__device__ float g_ffn[(size_t)B_ * L_ * F_];
__device__ float g_w[S_];
// transposed weights ([N][K] row-major), pre-rounded to tf32
__device__ float g_wdcT[3 * D_ * D_];                   // [o][tap][i]
__device__ float g_wdecT[6 * D_ * D_];                  // [s][o][tap][i]
__device__ float g_wbig[(size_t)6 * D_ * D_];           // [WqT(4 scales) ; Wk0T ; WvT]
__device__ float g_wkvT[(size_t)3 * 2 * D_ * D_];       // s=1..3: [WkT ; WvT]
__device__ float g_woT[D_ * D_];
__device__ float g_w1T[(size_t)D_ * F_];                // [F][D]
__device__ float g_w2T[(size_t)D_ * F_];                // [D][F]

// ---------------- helpers ----------------
__device__ __forceinline__ float tf32r(float x) {
    float r;
    asm("cvt.rna.tf32.f32 %0, %1;" : "=f"(r) : "f"(x));
    return r;
}
__device__ __forceinline__ void mma_tf32(float (&d)[4], const uint32_t (&a)[4],
                                         const uint32_t (&b)[2]) {
    asm volatile(
        "mma.sync.aligned.m16n8k8.row.col.f32.tf32.tf32.f32 "
        "{%0,%1,%2,%3}, {%4,%5,%6,%7}, {%8,%9}, {%0,%1,%2,%3};"
        : "+f"(d[0]), "+f"(d[1]), "+f"(d[2]), "+f"(d[3])
        : "r"(a[0]), "r"(a[1]), "r"(a[2]), "r"(a[3]), "r"(b[0]), "r"(b[1]));
}
__device__ __forceinline__ void cp16(float* smem, const float* g) {
    uint32_t s = (uint32_t)__cvta_generic_to_shared(smem);
    asm volatile("cp.async.cg.shared.global [%0], [%1], 16;" :: "r"(s), "l"(g));
}
#define CP_COMMIT() asm volatile("cp.async.commit_group;" ::: "memory")
#define CP_WAIT1()  asm volatile("cp.async.wait_group 1;" ::: "memory")
#define CP_WAIT0()  asm volatile("cp.async.wait_group 0;" ::: "memory")

#define SSTR 36               // R7-proven layout: 16B stores conflict-free
#define STAGE_FLOATS (2 * 128 * SSTR)          // 9216 floats = 36864 B
#define GEMM_SMEM_BYTES (3 * STAGE_FLOATS * 4) // 110592 (3-stage ring)

// ---------------- tf32 mma.sync GEMM (R11-proven: 8 warps x 64x32) ------------
// C[M,N] = act(alpha * A' @ BT^T [+bias] [+C]) ; row remap for conv-as-GEMM.
__global__ __launch_bounds__(256, 2) void mh_gemm_mma(
    const float* __restrict__ A, const float* __restrict__ BT, float* __restrict__ C,
    int M, int N, int Ktot, int lda, int KperTap, int tapOffRow,
    int Lout, int Lin, int strideL, int offRow,
    const float* __restrict__ bias, const float* __restrict__ alphaPtr,
    int accumulate, int act, int roundOut)
{
    extern __shared__ __align__(16) float dsm[];
    const int tid = threadIdx.x;
    const int lane = tid & 31;
    const int wid = tid >> 5;
    const int wr = wid >> 2;
    const int wc = wid & 3;
    const int rowBase = blockIdx.y * 128;
    const int colBase = blockIdx.x * 128;

    const float* aBase[4];
    const float* bBase[4];
    int sOff[4];
#pragma unroll
    for (int i = 0; i < 4; i++) {
        int idx = tid + i * 256;
        int row = idx >> 3, c4 = idx & 7;
        sOff[i] = row * SSTR + c4 * 4;
        int gr = rowBase + row;
        int ar = (gr / Lout) * Lin + (gr % Lout) * strideL + offRow;
        aBase[i] = A + (size_t)ar * lda + c4 * 4;
        bBase[i] = BT + (size_t)(colBase + row) * Ktot + c4 * 4;
    }

    float acc[4][4][4];
#pragma unroll
    for (int mt = 0; mt < 4; mt++)
#pragma unroll
        for (int nt = 0; nt < 4; nt++)
#pragma unroll
            for (int j = 0; j < 4; j++) acc[mt][nt][j] = 0.0f;

    const int T = Ktot / 32;

    auto load_stage = [&](int st, int k0) {
        int tap = k0 / KperTap;
        size_t aAdd = (size_t)tap * tapOffRow * lda + (k0 - tap * KperTap);
        float* As = dsm + st * STAGE_FLOATS;
        float* Bs = As + 128 * SSTR;
#pragma unroll
        for (int i = 0; i < 4; i++) {
            cp16(As + sOff[i], aBase[i] + aAdd);
            cp16(Bs + sOff[i], bBase[i] + k0);
        }
    };

    load_stage(0, 0); CP_COMMIT();
    if (T > 1) { load_stage(1, 32); CP_COMMIT(); }

    const int quad = lane >> 2;
    const int tq = lane & 3;

    for (int t = 0; t < T; t++) {
        if (t + 1 < T) CP_WAIT1(); else CP_WAIT0();
        __syncthreads();

        const int st = t % 3;
        const float* As = dsm + st * STAGE_FLOATS;
        const float* Bs = As + 128 * SSTR;
#pragma unroll
        for (int ks = 0; ks < 4; ks++) {
            uint32_t af[4][4], bf[4][2];
#pragma unroll
            for (int mt = 0; mt < 4; mt++) {
                int r = wr * 64 + mt * 16 + quad;
                const float* p = As + r * SSTR + ks * 8 + tq;
                af[mt][0] = __float_as_uint(p[0]);
                af[mt][1] = __float_as_uint(p[8 * SSTR]);
                af[mt][2] = __float_as_uint(p[4]);
                af[mt][3] = __float_as_uint(p[8 * SSTR + 4]);
            }
#pragma unroll
            for (int nt = 0; nt < 4; nt++) {
                int n = wc * 32 + nt * 8 + quad;
                const float* p = Bs + n * SSTR + ks * 8 + tq;
                bf[nt][0] = __float_as_uint(p[0]);
                bf[nt][1] = __float_as_uint(p[4]);
            }
#pragma unroll
            for (int mt = 0; mt < 4; mt++)
#pragma unroll
                for (int nt = 0; nt < 4; nt++)
                    mma_tf32(acc[mt][nt], af[mt], bf[nt]);
        }

        if (t + 2 < T) { load_stage((t + 2) % 3, (t + 2) * 32); CP_COMMIT(); }
    }

    const float alpha = alphaPtr ? __ldg(alphaPtr) : 1.0f;
#pragma unroll
    for (int mt = 0; mt < 4; mt++) {
#pragma unroll
        for (int nt = 0; nt < 4; nt++) {
            int row = rowBase + wr * 64 + mt * 16 + quad;
            int col = colBase + wc * 32 + nt * 8 + tq * 2;
#pragma unroll
            for (int h = 0; h < 2; h++) {
                int r = row + h * 8;
                float v0 = alpha * acc[mt][nt][h * 2 + 0];
                float v1 = alpha * acc[mt][nt][h * 2 + 1];
                if (bias) { v0 += bias[col]; v1 += bias[col + 1]; }
                float* cp = C + (size_t)r * N + col;
                if (accumulate) { v0 += cp[0]; v1 += cp[1]; }
                if (act == 1) { v0 = fmaxf(v0, 0.0f); v1 = fmaxf(v1, 0.0f); }
                else if (act == 2) {
                    v0 = 0.5f * v0 * (1.0f + erff(v0 * 0.70710678118654752440f));
                    v1 = 0.5f * v1 * (1.0f + erff(v1 * 0.70710678118654752440f));
                }
                if (roundOut) { v0 = tf32r(v0); v1 = tf32r(v1); }
                *(float2*)cp = make_float2(v0, v1);
            }
        }
    }
}

// ---------------- tensor-core flash attention (128q x 64k tiles) --------------
// 256 threads, 8 warps x 16 q-rows. K/V loaded once per 128 queries.
#define ASTR 72
#define QT_ 128
#define ATT_SMEM (((QT_ + 64 + 64 + QT_) * ASTR + 3 * QT_) * 4)  // 112128 B
__global__ __launch_bounds__(256) void mh_attn_mma(
    const float* __restrict__ q, int qld, int qoff,
    const float* __restrict__ kv, int kvld,
    float* __restrict__ o, int Ls,
    const float* __restrict__ alphaPtr, int accumulate)
{
    extern __shared__ __align__(16) float sm[];
    float* qs = sm;                    // 128 x 72
    float* ks = qs + QT_ * ASTR;       // 64 x 72
    float* vs = ks + 64 * ASTR;        // 64 x 72
    float* ps = vs + 64 * ASTR;        // 128 x 72
    float* s_max = ps + QT_ * ASTR;    // 128
    float* s_lsum = s_max + QT_;       // 128
    float* s_corr = s_lsum + QT_;      // 128

    const int tid = threadIdx.x;
    const int lane = tid & 31;
    const int w = tid >> 5;
    const int quad = lane >> 2, tq = lane & 3;
    const int b = blockIdx.z, h = blockIdx.y;
    const int q0 = blockIdx.x * QT_;
    const int rbase = w * 16;

    // load Q tile (128 rows x 64 dims): 2048 float4
#pragma unroll
    for (int it = 0; it < 8; it++) {
        int i = tid + it * 256;
        int r = i >> 4, dg = (i & 15) * 4;
        float4 t4 = *(const float4*)(q + (size_t)(b * L_ + q0 + r) * qld + qoff + h * 64 + dg);
        *(float4*)(qs + r * ASTR + dg) = t4;
    }
    if (tid < QT_) { s_max[tid] = -1e30f; s_lsum[tid] = 0.0f; }

    float oacc[8][4];
#pragma unroll
    for (int nt = 0; nt < 8; nt++)
#pragma unroll
        for (int j = 0; j < 4; j++) oacc[nt][j] = 0.0f;

    for (int kt = 0; kt < Ls; kt += 64) {
        __syncthreads();
        // load K,V chunk (64 keys x 64 dims each): 1024 float4 each
#pragma unroll
        for (int it = 0; it < 4; it++) {
            int i = tid + it * 256;
            int key = i >> 4, dg = (i & 15) * 4;
            const float* rowp = kv + (size_t)(b * Ls + kt + key) * kvld;
            *(float4*)(ks + key * ASTR + dg) = *(const float4*)(rowp + h * 64 + dg);
            *(float4*)(vs + key * ASTR + dg) = *(const float4*)(rowp + D_ + h * 64 + dg);
        }
        __syncthreads();

        // S = Q @ K^T (warp: its 16 q rows x 64 keys)
        float sacc[8][4];
#pragma unroll
        for (int nt = 0; nt < 8; nt++)
#pragma unroll
            for (int j = 0; j < 4; j++) sacc[nt][j] = 0.0f;
#pragma unroll
        for (int k8 = 0; k8 < 8; k8++) {
            uint32_t af[4];
            const float* qp = qs + (rbase + quad) * ASTR + k8 * 8 + tq;
            af[0] = __float_as_uint(qp[0]);
            af[1] = __float_as_uint(qp[8 * ASTR]);
            af[2] = __float_as_uint(qp[4]);
            af[3] = __float_as_uint(qp[8 * ASTR + 4]);
#pragma unroll
            for (int nt = 0; nt < 8; nt++) {
                uint32_t bf[2];
                const float* kp = ks + (nt * 8 + quad) * ASTR + k8 * 8 + tq;
                bf[0] = __float_as_uint(kp[0]);
                bf[1] = __float_as_uint(kp[4]);
                mma_tf32(sacc[nt], af, bf);
            }
        }
#pragma unroll
        for (int nt = 0; nt < 8; nt++) {
            float* p0 = ps + (rbase + quad) * ASTR + nt * 8 + 2 * tq;
            float* p1 = ps + (rbase + quad + 8) * ASTR + nt * 8 + 2 * tq;
            *(float2*)p0 = make_float2(sacc[nt][0] * 0.125f, sacc[nt][1] * 0.125f);
            *(float2*)p1 = make_float2(sacc[nt][2] * 0.125f, sacc[nt][3] * 0.125f);
        }
        __syncwarp();

        // online softmax on this warp's 16 rows
        {
            int r = rbase + (lane & 15);
            int half = lane >> 4;
            float* pr = ps + r * ASTR + half * 32;
            float mx = -1e30f;
#pragma unroll
            for (int j = 0; j < 32; j++) mx = fmaxf(mx, pr[j]);
            mx = fmaxf(mx, __shfl_xor_sync(0xFFFFFFFFu, mx, 16));
            float oldm = s_max[r];
            float newm = fmaxf(oldm, mx);
            float sum = 0.0f;
#pragma unroll
            for (int j = 0; j < 32; j++) {
                float p = __expf(pr[j] - newm);
                pr[j] = tf32r(p);
                sum += p;
            }
            sum += __shfl_xor_sync(0xFFFFFFFFu, sum, 16);
            if (half == 0) {
                float corr = __expf(oldm - newm);
                s_corr[r] = corr;
                s_lsum[r] = s_lsum[r] * corr + sum;
                s_max[r] = newm;
            }
        }
        __syncwarp();

        // rescale O, then O += P @ V
        {
            float c0 = s_corr[rbase + quad];
            float c1 = s_corr[rbase + quad + 8];
#pragma unroll
            for (int nt = 0; nt < 8; nt++) {
                oacc[nt][0] *= c0; oacc[nt][1] *= c0;
                oacc[nt][2] *= c1; oacc[nt][3] *= c1;
            }
        }
#pragma unroll
        for (int k8 = 0; k8 < 8; k8++) {
            uint32_t af[4];
            const float* pp = ps + (rbase + quad) * ASTR + k8 * 8 + tq;
            af[0] = __float_as_uint(pp[0]);
            af[1] = __float_as_uint(pp[8 * ASTR]);
            af[2] = __float_as_uint(pp[4]);
            af[3] = __float_as_uint(pp[8 * ASTR + 4]);
#pragma unroll
            for (int nt = 0; nt < 8; nt++) {
                uint32_t bf[2];
                const float* vp = vs + (k8 * 8 + tq) * ASTR + nt * 8 + quad;
                bf[0] = __float_as_uint(vp[0]);
                bf[1] = __float_as_uint(vp[4 * ASTR]);
                mma_tf32(oacc[nt], af, bf);
            }
        }
    }

    const float alpha = alphaPtr ? __ldg(alphaPtr) : 1.0f;
    const float l0 = alpha / s_lsum[rbase + quad];
    const float l1 = alpha / s_lsum[rbase + quad + 8];
    const int row0 = b * L_ + q0 + rbase + quad;
#pragma unroll
    for (int nt = 0; nt < 8; nt++) {
        int col = h * 64 + nt * 8 + 2 * tq;
        float* p0 = o + (size_t)row0 * D_ + col;
        float* p1 = o + (size_t)(row0 + 8) * D_ + col;
        float2 v0 = make_float2(oacc[nt][0] * l0, oacc[nt][1] * l0);
        float2 v1 = make_float2(oacc[nt][2] * l1, oacc[nt][3] * l1);
        if (accumulate) {
            v0.x += p0[0]; v0.y += p0[1];
            v1.x += p1[0]; v1.y += p1[1];
        }
        v0.x = tf32r(v0.x); v0.y = tf32r(v0.y);
        v1.x = tf32r(v1.x); v1.y = tf32r(v1.y);
        *(float2*)p0 = v0;
        *(float2*)p1 = v1;
    }
}

// ---------------- LayerNorm(a + b) ----------------
__global__ __launch_bounds__(256) void mh_ln(
    const float* __restrict__ a, const float* __restrict__ bsrc,
    const float* __restrict__ g, const float* __restrict__ be,
    float* __restrict__ out)
{
    __shared__ float r1[256], r2[256];
    int row = blockIdx.x;
    const float* ap = a + (size_t)row * D_;
    const float* bp = bsrc + (size_t)row * D_;
    float x[4];
    float s = 0.f, ss = 0.f;
#pragma unroll
    for (int i = 0; i < 4; i++) {
        int idx = threadIdx.x + i * 256;
        x[i] = ap[idx] + bp[idx];
        s += x[i];
        ss += x[i] * x[i];
    }
    int tid = threadIdx.x;
    r1[tid] = s;
    r2[tid] = ss;
    __syncthreads();
    for (int off = 128; off; off >>= 1) {
        if (tid < off) { r1[tid] += r1[tid + off]; r2[tid] += r2[tid + off]; }
        __syncthreads();
    }
    float mu = r1[0] * (1.0f / D_);
    float var = r2[0] * (1.0f / D_) - mu * mu;
    float rstd = rsqrtf(var + 1e-5f);
#pragma unroll
    for (int i = 0; i < 4; i++) {
        int idx = threadIdx.x + i * 256;
        out[(size_t)row * D_ + idx] = (x[i] - mu) * rstd * g[idx] + be[idx];
    }
}

// ---------------- misc small kernels ----------------
__global__ void mh_pad(const float* __restrict__ x, float* __restrict__ xpad)
{
    size_t i = (size_t)blockIdx.x * blockDim.x + threadIdx.x;
    if (i >= (size_t)B_ * LP_ * D_) return;
    int d = (int)(i % D_);
    size_t rl = i / D_;
    int l = (int)(rl % LP_);
    int b = (int)(rl / LP_);
    float val = 0.0f;
    if (l >= 2 && l < L_ + 2)
        val = tf32r(x[((size_t)b * L_ + (l - 2)) * D_ + d]);
    xpad[i] = val;
}

__global__ void mh_twdc(const float* __restrict__ W, float* __restrict__ out)
{
    int id = blockIdx.x * 256 + threadIdx.x;
    if (id >= 3 * D_ * D_) return;
    int i = id & (D_ - 1);
    int tmp = id >> 10;
    int t = tmp % 3;
    int o = tmp / 3;
    out[id] = tf32r(W[((size_t)o * D_ + i) * 3 + t]);
}

__global__ void mh_twdec(const float* __restrict__ W, float* __restrict__ out)
{
    int id = blockIdx.x * 256 + threadIdx.x;
    if (id >= 6 * D_ * D_) return;
    int i = id & (D_ - 1);
    int tmp = id >> 10;
    int t = tmp & 1;
    tmp >>= 1;
    int o = tmp & (D_ - 1);
    int s = tmp >> 10;
    out[id] = tf32r(W[(((size_t)s * D_ + o) * D_ + i) * 2 + t]);
}

// batched transpose with independent z-strides: dst[z][c][r] = tf32(src[z][r][c])
__global__ void mh_transpose(const float* __restrict__ src, float* __restrict__ dst,
                             int R, int C, size_t zsrc, size_t zdst)
{
    __shared__ float t[32][33];
    const float* sp = src + (size_t)blockIdx.z * zsrc;
    float* dp = dst + (size_t)blockIdx.z * zdst;
    int x = blockIdx.x * 32 + threadIdx.x;
    int y0 = blockIdx.y * 32 + threadIdx.y;
#pragma unroll
    for (int j = 0; j < 4; j++) {
        int y = y0 + j * 8;
        if (y < R && x < C) t[threadIdx.y + j * 8][threadIdx.x] = sp[(size_t)y * C + x];
    }
    __syncthreads();
    int x2 = blockIdx.y * 32 + threadIdx.x;
    int y2 = blockIdx.x * 32 + threadIdx.y;
#pragma unroll
    for (int j = 0; j < 4; j++) {
        int y = y2 + j * 8;
        if (y < C && x2 < R) dp[(size_t)y * R + x2] = tf32r(t[threadIdx.x][threadIdx.y + j * 8]);
    }
}

__global__ void mh_agg(const float* __restrict__ logits, float* __restrict__ w,
                       float* __restrict__ aux_out, int has_aux)
{
    if (threadIdx.x == 0 && blockIdx.x == 0) {
        float l[S_], m = -1e30f;
        for (int s = 0; s < S_; s++) { l[s] = logits[s]; m = fmaxf(m, l[s]); }
        float sum = 0.f;
        for (int s = 0; s < S_; s++) { l[s] = expf(l[s] - m); sum += l[s]; }
        float aux = 0.f;
        for (int s = 0; s < S_; s++) {
            float ws = l[s] / sum;
            w[s] = ws;
            aux -= ws * logf(ws + 1e-9f);
        }
        if (has_aux) *aux_out = aux;
    }
}

// ---------------- host launch ----------------
static void launch_tc(const float* A, const float* BT, float* C,
                      int M, int N, int Ktot, int lda, int KperTap, int tapOffRow,
                      int Lout, int Lin, int strideL, int offRow,
                      const float* bias, const float* alphaPtr,
                      int accumulate, int act, int roundOut)
{
    dim3 grid(N / 128, M / 128);
    mh_gemm_mma<<<grid, 256, GEMM_SMEM_BYTES>>>(
        A, BT, C, M, N, Ktot, lda, KperTap, tapOffRow,
        Lout, Lin, strideL, offRow, bias, alphaPtr, accumulate, act, roundOut);
}

extern "C" void kernel_launch(void* const* d_in, const int* in_sizes, int n_in,
                              void* d_out, int out_size)
{
    const float* x      = (const float*)d_in[0];
    const float* W_dc   = (const float*)d_in[1];
    const float* b_dc   = (const float*)d_in[2];
    const float* W_dec  = (const float*)d_in[3];
    const float* Wq     = (const float*)d_in[4];
    const float* Wk     = (const float*)d_in[5];
    const float* Wv     = (const float*)d_in[6];
    const float* Wo     = (const float*)d_in[7];
    const float* agl    = (const float*)d_in[8];
    const float* gamma1 = (const float*)d_in[9];
    const float* beta1  = (const float*)d_in[10];
    const float* gamma2 = (const float*)d_in[11];
    const float* beta2  = (const float*)d_in[12];
    const float* W1     = (const float*)d_in[13];
    const float* b1     = (const float*)d_in[14];
    const float* W2     = (const float*)d_in[15];
    const float* b2     = (const float*)d_in[16];
    float* out = (float*)d_out;

    cudaFuncSetAttribute(mh_gemm_mma, cudaFuncAttributeMaxDynamicSharedMemorySize,
                         GEMM_SMEM_BYTES);
    cudaFuncSetAttribute(mh_attn_mma, cudaFuncAttributeMaxDynamicSharedMemorySize,
                         ATT_SMEM);

    float *xpad, *xc, *sc1, *sc2, *sc3, *qkv, *kvb, *ob, *maha, *x1, *ffn, *wagg;
    float *wdcT, *wdecT, *wbig, *wkvT, *woT, *w1T, *w2T;
    cudaGetSymbolAddress((void**)&xpad, g_xpad);
    cudaGetSymbolAddress((void**)&xc, g_xc);
    cudaGetSymbolAddress((void**)&sc1, g_sc1);
    cudaGetSymbolAddress((void**)&sc2, g_sc2);
    cudaGetSymbolAddress((void**)&sc3, g_sc3);
    cudaGetSymbolAddress((void**)&qkv, g_qkv);
    cudaGetSymbolAddress((void**)&kvb, g_kvb);
    cudaGetSymbolAddress((void**)&ob, g_ob);
    cudaGetSymbolAddress((void**)&maha, g_maha);
    cudaGetSymbolAddress((void**)&x1, g_x1);
    cudaGetSymbolAddress((void**)&ffn, g_ffn);
    cudaGetSymbolAddress((void**)&wagg, g_w);
    cudaGetSymbolAddress((void**)&wdcT, g_wdcT);
    cudaGetSymbolAddress((void**)&wdecT, g_wdecT);
    cudaGetSymbolAddress((void**)&wbig, g_wbig);
    cudaGetSymbolAddress((void**)&wkvT, g_wkvT);
    cudaGetSymbolAddress((void**)&woT, g_woT);
    cudaGetSymbolAddress((void**)&w1T, g_w1T);
    cudaGetSymbolAddress((void**)&w2T, g_w2T);

    const int M = B_ * L_;
    const int has_aux = (out_size > B_ * L_ * D_) ? 1 : 0;
    const size_t DD = (size_t)D_ * D_;

    // prep: weight permutes/transposes (tf32-rounded), agg softmax, padded input
    mh_twdc<<<(3 * D_ * D_ + 255) / 256, 256>>>(W_dc, wdcT);
    mh_twdec<<<(6 * D_ * D_ + 255) / 256, 256>>>(W_dec, wdecT);
    {
        dim3 tb(32, 8);
        // wbig = [WqT for 4 scales ; Wk0T ; WvT]
        mh_transpose<<<dim3(32, 32, 4), tb>>>(Wq, wbig, D_, D_, DD, DD);
        mh_transpose<<<dim3(32, 32, 1), tb>>>(Wk, wbig + 4 * DD, D_, D_, 0, 0);
        mh_transpose<<<dim3(32, 32, 1), tb>>>(Wv, wbig + 5 * DD, D_, D_, 0, 0);
        // wkvT for s=1..3
        mh_transpose<<<dim3(32, 32, 3), tb>>>(Wk + DD, wkvT, D_, D_, DD, 2 * DD);
        mh_transpose<<<dim3(32, 32, 3), tb>>>(Wv, wkvT + DD, D_, D_, 0, 2 * DD);
        mh_transpose<<<dim3(32, 32, 1), tb>>>(Wo, woT, D_, D_, 0, 0);
        mh_transpose<<<dim3(128, 32, 1), tb>>>(W1, w1T, D_, F_, 0, 0);   // -> [F][D]
        mh_transpose<<<dim3(32, 128, 1), tb>>>(W2, w2T, F_, D_, 0, 0);   // -> [D][F]
    }
    mh_agg<<<1, 32>>>(agl, wagg, out + (size_t)B_ * L_ * D_, has_aux);
    mh_pad<<<(B_ * LP_ * D_ + 255) / 256, 256>>>(x, xpad);

    // 1. dilated conv (3 taps folded into K=3072) + bias + ReLU, tf32-rounded out
    launch_tc(xpad, wdcT, xc, M, D_, 3 * D_, D_, D_, 2,
              L_, LP_, 1, 0, b_dc, nullptr, 0, 1, 1);

    // 2. hierarchical decomposition (2 taps folded into K=2048)
    const float* scaleP[S_] = {xc, sc1, sc2, sc3};
    int scaleL[S_] = {L_, L_ / 2, L_ / 4, L_ / 8};
    {
        float* outs[3] = {sc1, sc2, sc3};
        for (int s = 0; s < 3; s++) {
            int Lin = scaleL[s], Lout = scaleL[s + 1];
            launch_tc(scaleP[s], wdecT + (size_t)s * 2 * DD, outs[s],
                      B_ * Lout, D_, 2 * D_, D_, D_, 1,
                      Lout, Lin, 2, 0, nullptr, nullptr, 0, 0, 1);
        }
    }

    // 3a. fused projection: all-scale Q + K0 + V0 in one GEMM -> qkv[M][6144]
    launch_tc(xc, wbig, qkv, M, 6 * D_, D_, D_, D_, 0,
              M, M, 1, 0, nullptr, nullptr, 0, 0, 1);

    // 3b. attention per scale (w_s-weighted, aggregated into ob; Wo applied once)
    for (int s = 0; s < S_; s++) {
        int Ls = scaleL[s];
        const float* kvp;
        int kvld;
        if (s == 0) { kvp = qkv + 4 * D_; kvld = 6 * D_; }
        else {
            int Mk = B_ * Ls;
            launch_tc(scaleP[s], wkvT + (size_t)(s - 1) * 2 * DD, kvb,
                      Mk, 2 * D_, D_, D_, D_, 0,
                      Mk, Mk, 1, 0, nullptr, nullptr, 0, 0, 1);
            kvp = kvb; kvld = 2 * D_;
        }
        dim3 agrid(L_ / QT_, H_, B_);
        mh_attn_mma<<<agrid, 256, ATT_SMEM>>>(qkv, 6 * D_, s * D_, kvp, kvld,
                                              ob, Ls, wagg + s, (s > 0) ? 1 : 0);
    }

    // 3c. shared output projection once: maha = ob @ Wo (fp32 out)
    launch_tc(ob, woT, maha, M, D_, D_, D_, D_, 0,
              M, M, 1, 0, nullptr, nullptr, 0, 0, 0);

    // 4. x1 = LN(residual + maha)  (fp32; tf32 truncation happens in-HW at MMA)
    mh_ln<<<M, 256>>>(x, maha, gamma1, beta1, x1);

    // 5. FFN: gelu(x1@W1+b1)@W2+b2, then out = LN(x1 + ffn)
    launch_tc(x1, w1T, ffn, M, F_, D_, D_, D_, 0, M, M, 1, 0, b1, nullptr, 0, 2, 1);
    launch_tc(ffn, w2T, ob, M, D_, F_, F_, F_, 0, M, M, 1, 0, b2, nullptr, 0, 0, 0);
    mh_ln<<<M, 256>>>(x1, ob, gamma2, beta2, out);
}

// round 17
// speedup vs baseline: 1.3973x; 1.3894x over previous
#include <cuda_runtime.h>
#include <cuda_fp16.h>
#include <cstdint>
#include <cstddef>

#define B_ 4
#define L_ 1024
#define D_ 1024
#define H_ 16
#define F_ 4096
#define S_ 4
#define LP_ (L_ + 4)

// ---------------- scratch (device globals; no allocation allowed) -------------
__device__ __align__(16) __half g_xpad[B_ * LP_ * D_];
__device__ __align__(16) __half g_xc[B_ * L_ * D_];
__device__ __align__(16) __half g_sc1[B_ * 512 * D_];
__device__ __align__(16) __half g_sc2[B_ * 256 * D_];
__device__ __align__(16) __half g_sc3[B_ * 128 * D_];
__device__ __align__(16) __half g_qkv[(size_t)B_ * L_ * 6 * D_];  // [Q x4 | K0 | V0]
__device__ __align__(16) __half g_kvb[(size_t)B_ * 512 * 2 * D_]; // K|V for s>=1
__device__ __align__(16) __half g_ob[B_ * L_ * D_];
__device__ __align__(16) __half g_x1h[B_ * L_ * D_];
__device__ __align__(16) __half g_ffn[(size_t)B_ * L_ * F_];
__device__ float  g_maha[B_ * L_ * D_];                // fp32 (LN inputs)
__device__ float  g_x1f[B_ * L_ * D_];
__device__ float  g_w[S_];
// transposed weights ([N][K] row-major), half
__device__ __align__(16) __half g_wdcT[3 * D_ * D_];
__device__ __align__(16) __half g_wdecT[6 * D_ * D_];
__device__ __align__(16) __half g_wbig[(size_t)6 * D_ * D_];      // [WqT x4 ; Wk0T ; WvT]
__device__ __align__(16) __half g_wkvT[(size_t)3 * 2 * D_ * D_];  // s=1..3: [WkT ; WvT]
__device__ __align__(16) __half g_woT[D_ * D_];
__device__ __align__(16) __half g_w1T[(size_t)D_ * F_];           // [F][D]
__device__ __align__(16) __half g_w2T[(size_t)D_ * F_];           // [D][F]

// ---------------- helpers ----------------
__device__ __forceinline__ float tf32r(float x) {
    float r;
    asm("cvt.rna.tf32.f32 %0, %1;" : "=f"(r) : "f"(x));
    return r;
}
__device__ __forceinline__ void mma_tf32(float (&d)[4], const uint32_t (&a)[4],
                                         const uint32_t (&b)[2]) {
    asm volatile(
        "mma.sync.aligned.m16n8k8.row.col.f32.tf32.tf32.f32 "
        "{%0,%1,%2,%3}, {%4,%5,%6,%7}, {%8,%9}, {%0,%1,%2,%3};"
        : "+f"(d[0]), "+f"(d[1]), "+f"(d[2]), "+f"(d[3])
        : "r"(a[0]), "r"(a[1]), "r"(a[2]), "r"(a[3]), "r"(b[0]), "r"(b[1]));
}
__device__ __forceinline__ void mma_f16(float (&d)[4], const uint32_t (&a)[4],
                                        const uint32_t (&b)[2]) {
    asm volatile(
        "mma.sync.aligned.m16n8k16.row.col.f32.f16.f16.f32 "
        "{%0,%1,%2,%3}, {%4,%5,%6,%7}, {%8,%9}, {%0,%1,%2,%3};"
        : "+f"(d[0]), "+f"(d[1]), "+f"(d[2]), "+f"(d[3])
        : "r"(a[0]), "r"(a[1]), "r"(a[2]), "r"(a[3]), "r"(b[0]), "r"(b[1]));
}
__device__ __forceinline__ void cp16(void* smem, const void* g) {
    uint32_t s = (uint32_t)__cvta_generic_to_shared(smem);
    asm volatile("cp.async.cg.shared.global [%0], [%1], 16;" :: "r"(s), "l"(g));
}
#define CP_COMMIT() asm volatile("cp.async.commit_group;" ::: "memory")
#define CP_WAIT1()  asm volatile("cp.async.wait_group 1;" ::: "memory")
#define CP_WAIT0()  asm volatile("cp.async.wait_group 0;" ::: "memory")

#define SH 40                       // halfs per smem row = 80B (16B-multiple!)
#define STAGE_H (2 * 128 * SH)      // A+B tiles per stage, halfs (20480 B)
#define GEMM_SMEM_BYTES (3 * STAGE_H * 2)  // 61440

// ---------------- fp16 mma.sync GEMM (8 warps x 64x32, 3-stage cp.async) ------
// C[M,N] = act(A' @ BT^T [+bias]) ; row remap for conv-as-GEMM.
__global__ __launch_bounds__(256, 2) void mh_gemm_h(
    const __half* __restrict__ A, const __half* __restrict__ BT, void* __restrict__ Cout,
    int M, int N, int Ktot, int lda, int KperTap, int tapOffRow,
    int Lout, int Lin, int strideL, int offRow,
    const float* __restrict__ bias, int act, int outHalf)
{
    extern __shared__ __align__(16) __half hsm[];
    const int tid = threadIdx.x;
    const int lane = tid & 31;
    const int wid = tid >> 5;
    const int wr = wid >> 2;
    const int wc = wid & 3;
    const int rowBase = blockIdx.y * 128;
    const int colBase = blockIdx.x * 128;

    // loader: A tile 128x32 halfs = 512 16B-chunks; 2 per thread per operand
    const __half* aBase[2];
    const __half* bBase[2];
    int sOff[2];
#pragma unroll
    for (int i = 0; i < 2; i++) {
        int idx = tid + i * 256;
        int row = idx >> 2, c8 = (idx & 3) * 8;
        sOff[i] = row * SH + c8;
        int gr = rowBase + row;
        int ar = (gr / Lout) * Lin + (gr % Lout) * strideL + offRow;
        aBase[i] = A + (size_t)ar * lda + c8;
        bBase[i] = BT + (size_t)(colBase + row) * Ktot + c8;
    }

    float acc[4][4][4];
#pragma unroll
    for (int mt = 0; mt < 4; mt++)
#pragma unroll
        for (int nt = 0; nt < 4; nt++)
#pragma unroll
            for (int j = 0; j < 4; j++) acc[mt][nt][j] = 0.0f;

    const int T = Ktot / 32;

    auto load_stage = [&](int st, int k0) {
        int tap = k0 / KperTap;
        size_t aAdd = (size_t)tap * tapOffRow * lda + (k0 - tap * KperTap);
        __half* As = hsm + st * STAGE_H;
        __half* Bs = As + 128 * SH;
#pragma unroll
        for (int i = 0; i < 2; i++) {
            cp16(As + sOff[i], aBase[i] + aAdd);
            cp16(Bs + sOff[i], bBase[i] + k0);
        }
    };

    load_stage(0, 0); CP_COMMIT();
    if (T > 1) { load_stage(1, 32); CP_COMMIT(); }

    const int quad = lane >> 2;
    const int tq = lane & 3;

    for (int t = 0; t < T; t++) {
        if (t + 1 < T) CP_WAIT1(); else CP_WAIT0();
        __syncthreads();

        const int st = t % 3;
        const __half* As = hsm + st * STAGE_H;
        const __half* Bs = As + 128 * SH;
#pragma unroll
        for (int ks = 0; ks < 2; ks++) {       // two k16 steps per 32-K chunk
            uint32_t af[4][4], bf[4][2];
#pragma unroll
            for (int mt = 0; mt < 4; mt++) {
                int r = wr * 64 + mt * 16 + quad;
                const __half* p = As + r * SH + ks * 16 + 2 * tq;
                af[mt][0] = *(const uint32_t*)(p);
                af[mt][1] = *(const uint32_t*)(p + 8 * SH);
                af[mt][2] = *(const uint32_t*)(p + 8);
                af[mt][3] = *(const uint32_t*)(p + 8 * SH + 8);
            }
#pragma unroll
            for (int nt = 0; nt < 4; nt++) {
                int n = wc * 32 + nt * 8 + quad;
                const __half* p = Bs + n * SH + ks * 16 + 2 * tq;
                bf[nt][0] = *(const uint32_t*)(p);
                bf[nt][1] = *(const uint32_t*)(p + 8);
            }
#pragma unroll
            for (int mt = 0; mt < 4; mt++)
#pragma unroll
                for (int nt = 0; nt < 4; nt++)
                    mma_f16(acc[mt][nt], af[mt], bf[nt]);
        }

        if (t + 2 < T) { load_stage((t + 2) % 3, (t + 2) * 32); CP_COMMIT(); }
    }

#pragma unroll
    for (int mt = 0; mt < 4; mt++) {
#pragma unroll
        for (int nt = 0; nt < 4; nt++) {
            int row = rowBase + wr * 64 + mt * 16 + quad;
            int col = colBase + wc * 32 + nt * 8 + tq * 2;
#pragma unroll
            for (int h2 = 0; h2 < 2; h2++) {
                int r = row + h2 * 8;
                float v0 = acc[mt][nt][h2 * 2 + 0];
                float v1 = acc[mt][nt][h2 * 2 + 1];
                if (bias) { v0 += bias[col]; v1 += bias[col + 1]; }
                if (act == 1) { v0 = fmaxf(v0, 0.0f); v1 = fmaxf(v1, 0.0f); }
                else if (act == 2) {
                    v0 = 0.5f * v0 * (1.0f + erff(v0 * 0.70710678118654752440f));
                    v1 = 0.5f * v1 * (1.0f + erff(v1 * 0.70710678118654752440f));
                }
                if (outHalf) {
                    *(__half2*)((__half*)Cout + (size_t)r * N + col) =
                        __floats2half2_rn(v0, v1);
                } else {
                    *(float2*)((float*)Cout + (size_t)r * N + col) = make_float2(v0, v1);
                }
            }
        }
    }
}

// ---------------- tensor-core flash attention (128q x 64k tiles, tf32 math) ---
// q/kv are half in global; converted to float in smem. o written half.
#define ASTR 72
#define QT_ 128
#define ATT_SMEM (((QT_ + 64 + 64 + QT_) * ASTR + 3 * QT_) * 4)  // 112128 B
__global__ __launch_bounds__(256) void mh_attn_mma(
    const __half* __restrict__ q, int qld, int qoff,
    const __half* __restrict__ kv, int kvld,
    __half* __restrict__ o, int Ls,
    const float* __restrict__ alphaPtr, int accumulate)
{
    extern __shared__ __align__(16) float sm[];
    float* qs = sm;                    // 128 x 72
    float* ks = qs + QT_ * ASTR;       // 64 x 72
    float* vs = ks + 64 * ASTR;        // 64 x 72
    float* ps = vs + 64 * ASTR;        // 128 x 72
    float* s_max = ps + QT_ * ASTR;
    float* s_lsum = s_max + QT_;
    float* s_corr = s_lsum + QT_;

    const int tid = threadIdx.x;
    const int lane = tid & 31;
    const int w = tid >> 5;
    const int quad = lane >> 2, tq = lane & 3;
    const int b = blockIdx.z, h = blockIdx.y;
    const int q0 = blockIdx.x * QT_;
    const int rbase = w * 16;

    // load Q tile (128 rows x 64 halfs -> float smem)
#pragma unroll
    for (int it = 0; it < 4; it++) {
        int i = tid + it * 256;
        int r = i >> 3, d8 = (i & 7) * 8;
        uint4 raw = *(const uint4*)(q + (size_t)(b * L_ + q0 + r) * qld + qoff + h * 64 + d8);
        float2 f0 = __half22float2(*(__half2*)&raw.x);
        float2 f1 = __half22float2(*(__half2*)&raw.y);
        float2 f2 = __half22float2(*(__half2*)&raw.z);
        float2 f3 = __half22float2(*(__half2*)&raw.w);
        float* dst = qs + r * ASTR + d8;
        *(float4*)dst = make_float4(f0.x, f0.y, f1.x, f1.y);
        *(float4*)(dst + 4) = make_float4(f2.x, f2.y, f3.x, f3.y);
    }
    if (tid < QT_) { s_max[tid] = -1e30f; s_lsum[tid] = 0.0f; }

    float oacc[8][4];
#pragma unroll
    for (int nt = 0; nt < 8; nt++)
#pragma unroll
        for (int j = 0; j < 4; j++) oacc[nt][j] = 0.0f;

    for (int kt = 0; kt < Ls; kt += 64) {
        __syncthreads();
#pragma unroll
        for (int it = 0; it < 2; it++) {
            int i = tid + it * 256;
            int key = i >> 3, d8 = (i & 7) * 8;
            const __half* rowp = kv + (size_t)(b * Ls + kt + key) * kvld;
            uint4 kraw = *(const uint4*)(rowp + h * 64 + d8);
            uint4 vraw = *(const uint4*)(rowp + D_ + h * 64 + d8);
            {
                float2 f0 = __half22float2(*(__half2*)&kraw.x);
                float2 f1 = __half22float2(*(__half2*)&kraw.y);
                float2 f2 = __half22float2(*(__half2*)&kraw.z);
                float2 f3 = __half22float2(*(__half2*)&kraw.w);
                float* kd = ks + key * ASTR + d8;
                *(float4*)kd = make_float4(f0.x, f0.y, f1.x, f1.y);
                *(float4*)(kd + 4) = make_float4(f2.x, f2.y, f3.x, f3.y);
            }
            {
                float2 f0 = __half22float2(*(__half2*)&vraw.x);
                float2 f1 = __half22float2(*(__half2*)&vraw.y);
                float2 f2 = __half22float2(*(__half2*)&vraw.z);
                float2 f3 = __half22float2(*(__half2*)&vraw.w);
                float* vd = vs + key * ASTR + d8;
                *(float4*)vd = make_float4(f0.x, f0.y, f1.x, f1.y);
                *(float4*)(vd + 4) = make_float4(f2.x, f2.y, f3.x, f3.y);
            }
        }
        __syncthreads();

        // S = Q @ K^T
        float sacc[8][4];
#pragma unroll
        for (int nt = 0; nt < 8; nt++)
#pragma unroll
            for (int j = 0; j < 4; j++) sacc[nt][j] = 0.0f;
#pragma unroll
        for (int k8 = 0; k8 < 8; k8++) {
            uint32_t af[4];
            const float* qp = qs + (rbase + quad) * ASTR + k8 * 8 + tq;
            af[0] = __float_as_uint(qp[0]);
            af[1] = __float_as_uint(qp[8 * ASTR]);
            af[2] = __float_as_uint(qp[4]);
            af[3] = __float_as_uint(qp[8 * ASTR + 4]);
#pragma unroll
            for (int nt = 0; nt < 8; nt++) {
                uint32_t bf[2];
                const float* kp = ks + (nt * 8 + quad) * ASTR + k8 * 8 + tq;
                bf[0] = __float_as_uint(kp[0]);
                bf[1] = __float_as_uint(kp[4]);
                mma_tf32(sacc[nt], af, bf);
            }
        }
#pragma unroll
        for (int nt = 0; nt < 8; nt++) {
            float* p0 = ps + (rbase + quad) * ASTR + nt * 8 + 2 * tq;
            float* p1 = ps + (rbase + quad + 8) * ASTR + nt * 8 + 2 * tq;
            *(float2*)p0 = make_float2(sacc[nt][0] * 0.125f, sacc[nt][1] * 0.125f);
            *(float2*)p1 = make_float2(sacc[nt][2] * 0.125f, sacc[nt][3] * 0.125f);
        }
        __syncwarp();

        // online softmax (warp-local rows)
        {
            int r = rbase + (lane & 15);
            int half_ = lane >> 4;
            float* pr = ps + r * ASTR + half_ * 32;
            float mx = -1e30f;
#pragma unroll
            for (int j = 0; j < 32; j++) mx = fmaxf(mx, pr[j]);
            mx = fmaxf(mx, __shfl_xor_sync(0xFFFFFFFFu, mx, 16));
            float oldm = s_max[r];
            float newm = fmaxf(oldm, mx);
            float sum = 0.0f;
#pragma unroll
            for (int j = 0; j < 32; j++) {
                float p = __expf(pr[j] - newm);
                pr[j] = tf32r(p);
                sum += p;
            }
            sum += __shfl_xor_sync(0xFFFFFFFFu, sum, 16);
            if (half_ == 0) {
                float corr = __expf(oldm - newm);
                s_corr[r] = corr;
                s_lsum[r] = s_lsum[r] * corr + sum;
                s_max[r] = newm;
            }
        }
        __syncwarp();

        // O = O*corr + P @ V
        {
            float c0 = s_corr[rbase + quad];
            float c1 = s_corr[rbase + quad + 8];
#pragma unroll
            for (int nt = 0; nt < 8; nt++) {
                oacc[nt][0] *= c0; oacc[nt][1] *= c0;
                oacc[nt][2] *= c1; oacc[nt][3] *= c1;
            }
        }
#pragma unroll
        for (int k8 = 0; k8 < 8; k8++) {
            uint32_t af[4];
            const float* pp = ps + (rbase + quad) * ASTR + k8 * 8 + tq;
            af[0] = __float_as_uint(pp[0]);
            af[1] = __float_as_uint(pp[8 * ASTR]);
            af[2] = __float_as_uint(pp[4]);
            af[3] = __float_as_uint(pp[8 * ASTR + 4]);
#pragma unroll
            for (int nt = 0; nt < 8; nt++) {
                uint32_t bf[2];
                const float* vp = vs + (k8 * 8 + tq) * ASTR + nt * 8 + quad;
                bf[0] = __float_as_uint(vp[0]);
                bf[1] = __float_as_uint(vp[4 * ASTR]);
                mma_tf32(oacc[nt], af, bf);
            }
        }
    }

    const float alpha = alphaPtr ? __ldg(alphaPtr) : 1.0f;
    const float l0 = alpha / s_lsum[rbase + quad];
    const float l1 = alpha / s_lsum[rbase + quad + 8];
    const int row0 = b * L_ + q0 + rbase + quad;
#pragma unroll
    for (int nt = 0; nt < 8; nt++) {
        int col = h * 64 + nt * 8 + 2 * tq;
        __half* p0 = o + (size_t)row0 * D_ + col;
        __half* p1 = o + (size_t)(row0 + 8) * D_ + col;
        float2 v0 = make_float2(oacc[nt][0] * l0, oacc[nt][1] * l0);
        float2 v1 = make_float2(oacc[nt][2] * l1, oacc[nt][3] * l1);
        if (accumulate) {
            float2 o0 = __half22float2(*(__half2*)p0);
            float2 o1 = __half22float2(*(__half2*)p1);
            v0.x += o0.x; v0.y += o0.y;
            v1.x += o1.x; v1.y += o1.y;
        }
        *(__half2*)p0 = __floats2half2_rn(v0.x, v0.y);
        *(__half2*)p1 = __floats2half2_rn(v1.x, v1.y);
    }
}

// ---------------- LayerNorm(a + b): fp32 out + optional half out --------------
__global__ __launch_bounds__(256) void mh_ln(
    const float* __restrict__ a, const float* __restrict__ bsrc,
    const float* __restrict__ g, const float* __restrict__ be,
    float* __restrict__ outf, __half* __restrict__ outh)
{
    __shared__ float r1[256], r2[256];
    int row = blockIdx.x;
    const float* ap = a + (size_t)row * D_;
    const float* bp = bsrc + (size_t)row * D_;
    float x[4];
    float s = 0.f, ss = 0.f;
#pragma unroll
    for (int i = 0; i < 4; i++) {
        int idx = threadIdx.x + i * 256;
        x[i] = ap[idx] + bp[idx];
        s += x[i];
        ss += x[i] * x[i];
    }
    int tid = threadIdx.x;
    r1[tid] = s;
    r2[tid] = ss;
    __syncthreads();
    for (int off = 128; off; off >>= 1) {
        if (tid < off) { r1[tid] += r1[tid + off]; r2[tid] += r2[tid + off]; }
        __syncthreads();
    }
    float mu = r1[0] * (1.0f / D_);
    float var = r2[0] * (1.0f / D_) - mu * mu;
    float rstd = rsqrtf(var + 1e-5f);
#pragma unroll
    for (int i = 0; i < 4; i++) {
        int idx = threadIdx.x + i * 256;
        float v = (x[i] - mu) * rstd * g[idx] + be[idx];
        outf[(size_t)row * D_ + idx] = v;
        if (outh) outh[(size_t)row * D_ + idx] = __float2half_rn(v);
    }
}

// ---------------- misc small kernels ----------------
__global__ void mh_pad(const float* __restrict__ x, __half* __restrict__ xpad)
{
    size_t i = (size_t)blockIdx.x * blockDim.x + threadIdx.x;
    if (i >= (size_t)B_ * LP_ * D_) return;
    int d = (int)(i % D_);
    size_t rl = i / D_;
    int l = (int)(rl % LP_);
    int b = (int)(rl / LP_);
    float val = 0.0f;
    if (l >= 2 && l < L_ + 2)
        val = x[((size_t)b * L_ + (l - 2)) * D_ + d];
    xpad[i] = __float2half_rn(val);
}

__global__ void mh_twdc(const float* __restrict__ W, __half* __restrict__ out)
{
    int id = blockIdx.x * 256 + threadIdx.x;
    if (id >= 3 * D_ * D_) return;
    int i = id & (D_ - 1);
    int tmp = id >> 10;
    int t = tmp % 3;
    int o = tmp / 3;
    out[id] = __float2half_rn(W[((size_t)o * D_ + i) * 3 + t]);
}

__global__ void mh_twdec(const float* __restrict__ W, __half* __restrict__ out)
{
    int id = blockIdx.x * 256 + threadIdx.x;
    if (id >= 6 * D_ * D_) return;
    int i = id & (D_ - 1);
    int tmp = id >> 10;
    int t = tmp & 1;
    tmp >>= 1;
    int o = tmp & (D_ - 1);
    int s = tmp >> 10;
    out[id] = __float2half_rn(W[(((size_t)s * D_ + o) * D_ + i) * 2 + t]);
}

// batched transpose with z-strides: dst[z][c][r] = half(src[z][r][c])
__global__ void mh_transpose(const float* __restrict__ src, __half* __restrict__ dst,
                             int R, int C, size_t zsrc, size_t zdst)
{
    __shared__ float t[32][33];
    const float* sp = src + (size_t)blockIdx.z * zsrc;
    __half* dp = dst + (size_t)blockIdx.z * zdst;
    int x = blockIdx.x * 32 + threadIdx.x;
    int y0 = blockIdx.y * 32 + threadIdx.y;
#pragma unroll
    for (int j = 0; j < 4; j++) {
        int y = y0 + j * 8;
        if (y < R && x < C) t[threadIdx.y + j * 8][threadIdx.x] = sp[(size_t)y * C + x];
    }
    __syncthreads();
    int x2 = blockIdx.y * 32 + threadIdx.x;
    int y2 = blockIdx.x * 32 + threadIdx.y;
#pragma unroll
    for (int j = 0; j < 4; j++) {
        int y = y2 + j * 8;
        if (y < C && x2 < R)
            dp[(size_t)y * R + x2] = __float2half_rn(t[threadIdx.x][threadIdx.y + j * 8]);
    }
}

__global__ void mh_agg(const float* __restrict__ logits, float* __restrict__ w,
                       float* __restrict__ aux_out, int has_aux)
{
    if (threadIdx.x == 0 && blockIdx.x == 0) {
        float l[S_], m = -1e30f;
        for (int s = 0; s < S_; s++) { l[s] = logits[s]; m = fmaxf(m, l[s]); }
        float sum = 0.f;
        for (int s = 0; s < S_; s++) { l[s] = expf(l[s] - m); sum += l[s]; }
        float aux = 0.f;
        for (int s = 0; s < S_; s++) {
            float ws = l[s] / sum;
            w[s] = ws;
            aux -= ws * logf(ws + 1e-9f);
        }
        if (has_aux) *aux_out = aux;
    }
}

// ---------------- host launch ----------------
static void launch_tc(const __half* A, const __half* BT, void* C,
                      int M, int N, int Ktot, int lda, int KperTap, int tapOffRow,
                      int Lout, int Lin, int strideL, int offRow,
                      const float* bias, int act, int outHalf)
{
    dim3 grid(N / 128, M / 128);
    mh_gemm_h<<<grid, 256, GEMM_SMEM_BYTES>>>(
        A, BT, C, M, N, Ktot, lda, KperTap, tapOffRow,
        Lout, Lin, strideL, offRow, bias, act, outHalf);
}

extern "C" void kernel_launch(void* const* d_in, const int* in_sizes, int n_in,
                              void* d_out, int out_size)
{
    const float* x      = (const float*)d_in[0];
    const float* W_dc   = (const float*)d_in[1];
    const float* b_dc   = (const float*)d_in[2];
    const float* W_dec  = (const float*)d_in[3];
    const float* Wq     = (const float*)d_in[4];
    const float* Wk     = (const float*)d_in[5];
    const float* Wv     = (const float*)d_in[6];
    const float* Wo     = (const float*)d_in[7];
    const float* agl    = (const float*)d_in[8];
    const float* gamma1 = (const float*)d_in[9];
    const float* beta1  = (const float*)d_in[10];
    const float* gamma2 = (const float*)d_in[11];
    const float* beta2  = (const float*)d_in[12];
    const float* W1     = (const float*)d_in[13];
    const float* b1     = (const float*)d_in[14];
    const float* W2     = (const float*)d_in[15];
    const float* b2     = (const float*)d_in[16];
    float* out = (float*)d_out;

    cudaFuncSetAttribute(mh_gemm_h, cudaFuncAttributeMaxDynamicSharedMemorySize,
                         GEMM_SMEM_BYTES);
    cudaFuncSetAttribute(mh_attn_mma, cudaFuncAttributeMaxDynamicSharedMemorySize,
                         ATT_SMEM);

    __half *xpad, *xc, *sc1, *sc2, *sc3, *qkv, *kvb, *ob, *x1h, *ffn;
    __half *wdcT, *wdecT, *wbig, *wkvT, *woT, *w1T, *w2T;
    float *maha, *x1f, *wagg;
    cudaGetSymbolAddress((void**)&xpad, g_xpad);
    cudaGetSymbolAddress((void**)&xc, g_xc);
    cudaGetSymbolAddress((void**)&sc1, g_sc1);
    cudaGetSymbolAddress((void**)&sc2, g_sc2);
    cudaGetSymbolAddress((void**)&sc3, g_sc3);
    cudaGetSymbolAddress((void**)&qkv, g_qkv);
    cudaGetSymbolAddress((void**)&kvb, g_kvb);
    cudaGetSymbolAddress((void**)&ob, g_ob);
    cudaGetSymbolAddress((void**)&x1h, g_x1h);
    cudaGetSymbolAddress((void**)&ffn, g_ffn);
    cudaGetSymbolAddress((void**)&maha, g_maha);
    cudaGetSymbolAddress((void**)&x1f, g_x1f);
    cudaGetSymbolAddress((void**)&wagg, g_w);
    cudaGetSymbolAddress((void**)&wdcT, g_wdcT);
    cudaGetSymbolAddress((void**)&wdecT, g_wdecT);
    cudaGetSymbolAddress((void**)&wbig, g_wbig);
    cudaGetSymbolAddress((void**)&wkvT, g_wkvT);
    cudaGetSymbolAddress((void**)&woT, g_woT);
    cudaGetSymbolAddress((void**)&w1T, g_w1T);
    cudaGetSymbolAddress((void**)&w2T, g_w2T);

    const int M = B_ * L_;
    const int has_aux = (out_size > B_ * L_ * D_) ? 1 : 0;
    const size_t DD = (size_t)D_ * D_;

    // prep: weight permutes/transposes (-> half), agg softmax, padded input
    mh_twdc<<<(3 * D_ * D_ + 255) / 256, 256>>>(W_dc, wdcT);
    mh_twdec<<<(6 * D_ * D_ + 255) / 256, 256>>>(W_dec, wdecT);
    {
        dim3 tb(32, 8);
        mh_transpose<<<dim3(32, 32, 4), tb>>>(Wq, wbig, D_, D_, DD, DD);
        mh_transpose<<<dim3(32, 32, 1), tb>>>(Wk, wbig + 4 * DD, D_, D_, 0, 0);
        mh_transpose<<<dim3(32, 32, 1), tb>>>(Wv, wbig + 5 * DD, D_, D_, 0, 0);
        mh_transpose<<<dim3(32, 32, 3), tb>>>(Wk + DD, wkvT, D_, D_, DD, 2 * DD);
        mh_transpose<<<dim3(32, 32, 3), tb>>>(Wv, wkvT + DD, D_, D_, 0, 2 * DD);
        mh_transpose<<<dim3(32, 32, 1), tb>>>(Wo, woT, D_, D_, 0, 0);
        mh_transpose<<<dim3(128, 32, 1), tb>>>(W1, w1T, D_, F_, 0, 0);   // -> [F][D]
        mh_transpose<<<dim3(32, 128, 1), tb>>>(W2, w2T, F_, D_, 0, 0);   // -> [D][F]
    }
    mh_agg<<<1, 32>>>(agl, wagg, out + (size_t)B_ * L_ * D_, has_aux);
    mh_pad<<<(B_ * LP_ * D_ + 255) / 256, 256>>>(x, xpad);

    // 1. dilated conv (3 taps folded into K=3072) + bias + ReLU -> half
    launch_tc(xpad, wdcT, xc, M, D_, 3 * D_, D_, D_, 2,
              L_, LP_, 1, 0, b_dc, 1, 1);

    // 2. hierarchical decomposition (2 taps folded into K=2048) -> half
    const __half* scaleP[S_] = {xc, sc1, sc2, sc3};
    int scaleL[S_] = {L_, L_ / 2, L_ / 4, L_ / 8};
    {
        __half* outs[3] = {sc1, sc2, sc3};
        for (int s = 0; s < 3; s++) {
            int Lin = scaleL[s], Lout = scaleL[s + 1];
            launch_tc(scaleP[s], wdecT + (size_t)s * 2 * DD, outs[s],
                      B_ * Lout, D_, 2 * D_, D_, D_, 1,
                      Lout, Lin, 2, 0, nullptr, 0, 1);
        }
    }

    // 3a. fused projection: all-scale Q + K0 + V0 -> qkv[M][6144] half
    launch_tc(xc, wbig, qkv, M, 6 * D_, D_, D_, D_, 0,
              M, M, 1, 0, nullptr, 0, 1);

    // 3b. attention per scale (w_s-weighted, aggregated into ob half)
    for (int s = 0; s < S_; s++) {
        int Ls = scaleL[s];
        const __half* kvp;
        int kvld;
        if (s == 0) { kvp = qkv + 4 * D_; kvld = 6 * D_; }
        else {
            int Mk = B_ * Ls;
            launch_tc(scaleP[s], wkvT + (size_t)(s - 1) * 2 * DD, kvb,
                      Mk, 2 * D_, D_, D_, D_, 0,
                      Mk, Mk, 1, 0, nullptr, 0, 1);
            kvp = kvb; kvld = 2 * D_;
        }
        dim3 agrid(L_ / QT_, H_, B_);
        mh_attn_mma<<<agrid, 256, ATT_SMEM>>>(qkv, 6 * D_, s * D_, kvp, kvld,
                                              ob, Ls, wagg + s, (s > 0) ? 1 : 0);
    }

    // 3c. shared output projection once: maha = ob @ Wo -> fp32
    launch_tc(ob, woT, maha, M, D_, D_, D_, D_, 0,
              M, M, 1, 0, nullptr, 0, 0);

    // 4. x1 = LN(x + maha) -> fp32 (x1f) + half (x1h)
    mh_ln<<<M, 256>>>(x, maha, gamma1, beta1, x1f, x1h);

    // 5. FFN: gelu(x1@W1+b1) -> half; @W2+b2 -> fp32 (reuse maha); LN2 -> out
    launch_tc(x1h, w1T, ffn, M, F_, D_, D_, D_, 0, M, M, 1, 0, b1, 2, 1);
    launch_tc(ffn, w2T, maha, M, D_, F_, F_, F_, 0, M, M, 1, 0, b2, 0, 0);
    mh_ln<<<M, 256>>>(x1f, maha, gamma2, beta2, out, nullptr);
}